// round 1
// baseline (speedup 1.0000x reference)
#include <cuda_runtime.h>
#include <cstdint>

// GCN: out = relu( Dn^-1/2 A Dn^-1/2 (G @ W) + bias ), plus verbatim adj copy.
// B=16, N=4096, F_IN=F_OUT=64.
//
// Pipeline (all on default stream, graph-capturable, no allocations):
//   1) rowsum_kernel:  g_dinv[n] = rsqrt(max-guarded rowsum(adj[n,:]))
//   2) support_kernel: g_S2[b,m,o] = dinv[m] * sum_i graph[b,m,i]*W[i,o]
//   3) gemm_kernel:    out[b,n,o] = relu(dinv[n] * sum_m adj[n,m]*S2[b,m,o] + bias[o])
//      (viewed as C[4096 x 1024] = adj[4096x4096] @ S2'[4096x1024], 128x128 tiles)
//   4) copy_adj:       adj -> d_out tail

#define NN 4096
#define FF 64
#define BB 16

__device__ float g_dinv[NN];
__device__ float g_S2[(size_t)BB * NN * FF];   // 16 MB scratch, [b][m][o]

// ---------------------------------------------------------------------------
// 1) row sums -> d^{-1/2}
// ---------------------------------------------------------------------------
__global__ void rowsum_kernel(const float* __restrict__ adj) {
    __shared__ float red[8];
    int row = blockIdx.x;
    const float4* r = (const float4*)(adj + (size_t)row * NN);
    float s = 0.f;
    for (int i = threadIdx.x; i < NN / 4; i += 256) {
        float4 v = r[i];
        s += (v.x + v.y) + (v.z + v.w);
    }
    #pragma unroll
    for (int off = 16; off; off >>= 1) s += __shfl_xor_sync(0xffffffffu, s, off);
    if ((threadIdx.x & 31) == 0) red[threadIdx.x >> 5] = s;
    __syncthreads();
    if (threadIdx.x < 8) {
        s = red[threadIdx.x];
        #pragma unroll
        for (int off = 4; off; off >>= 1) s += __shfl_xor_sync(0xffu, s, off);
        if (threadIdx.x == 0) {
            if (s == 0.f) s = 1.f;           // isolated-node guard (matches ref)
            g_dinv[row] = rsqrtf(s);
        }
    }
}

// ---------------------------------------------------------------------------
// 2) support = (graph @ W) * dinv[m]
//    Block: 256 threads = 4 row-groups x 64 output cols. W column lives in regs.
// ---------------------------------------------------------------------------
__global__ __launch_bounds__(256)
void support_kernel(const float* __restrict__ graph, const float* __restrict__ weight) {
    __shared__ float g_s[4][FF];
    int tid = threadIdx.x;
    int o   = tid & 63;
    int grp = tid >> 6;

    float w[FF];
    #pragma unroll
    for (int i = 0; i < FF; i++) w[i] = weight[i * FF + o];

    int Rbase = blockIdx.x * 64;   // 64 flat rows (b*N+m) per block
    for (int it = 0; it < 16; it++) {
        int R = Rbase + it * 4 + grp;
        g_s[grp][o] = graph[(size_t)R * FF + o];
        __syncthreads();
        float acc = 0.f;
        #pragma unroll
        for (int i = 0; i < FF; i++) acc = fmaf(g_s[grp][i], w[i], acc);
        int m = R & (NN - 1);
        g_S2[(size_t)R * FF + o] = acc * g_dinv[m];
        __syncthreads();
    }
}

// ---------------------------------------------------------------------------
// 3) main GEMM: C[n, col] = sum_m adj[n,m] * S2[m, col], col = b*64+o
//    128x128 tile / CTA, 256 threads, 8x8 per thread, BK=16, double-buffered.
// ---------------------------------------------------------------------------
#define BK 16

__global__ __launch_bounds__(256, 2)
void gemm_kernel(const float* __restrict__ adj,
                 const float* __restrict__ bias,
                 float* __restrict__ out) {
    __shared__ float sA[2][BK * 128];   // [k][row]
    __shared__ float sB[2][BK * 128];   // [k][col]

    int tid = threadIdx.x;
    int bx = blockIdx.x;   // col block 0..7   (1024/128)
    int by = blockIdx.y;   // row block 0..31  (4096/128)

    // --- global A load mapping: 128 rows x 16 k = 512 float4, 2 per thread
    int a_row = tid >> 1;                 // 0..127
    int a_kq  = (tid & 1) * 8;            // k offset {0, 8}
    const float* a_ptr = adj + (size_t)(by * 128 + a_row) * NN + a_kq;

    // --- global B load mapping: 16 m x 128 cols = 512 float4, 2 per thread
    int b_m  = tid >> 4;                  // 0..15
    int b_c  = (tid & 15) * 8;            // col offset in tile {0..120}
    int colB = bx * 128 + b_c;            // global col; (colB&63)<=56 so 8 floats stay in one b-slice
    const float* b_ptr = g_S2 + ((size_t)(colB >> 6)) * ((size_t)NN * FF)
                              + (size_t)b_m * FF + (colB & 63);

    float4 pa0, pa1, pb0, pb1;
    const int T = NN / BK;  // 256 k-tiles

    // prefetch tile 0
    pa0 = *(const float4*)(a_ptr);
    pa1 = *(const float4*)(a_ptr + 4);
    pb0 = *(const float4*)(b_ptr);
    pb1 = *(const float4*)(b_ptr + 4);

    // store tile 0 -> buf 0
    {
        float* s = &sA[0][a_kq * 128 + a_row];
        s[0*128] = pa0.x; s[1*128] = pa0.y; s[2*128] = pa0.z; s[3*128] = pa0.w;
        s[4*128] = pa1.x; s[5*128] = pa1.y; s[6*128] = pa1.z; s[7*128] = pa1.w;
        *(float4*)&sB[0][b_m * 128 + b_c]     = pb0;
        *(float4*)&sB[0][b_m * 128 + b_c + 4] = pb1;
    }
    __syncthreads();

    int ty = tid >> 4, tx = tid & 15;
    int row0 = ty * 8, col0 = tx * 8;

    float acc[8][8];
    #pragma unroll
    for (int i = 0; i < 8; i++)
        #pragma unroll
        for (int j = 0; j < 8; j++) acc[i][j] = 0.f;

    #pragma unroll 1
    for (int kt = 0; kt < T; kt++) {
        int buf = kt & 1;
        bool more = (kt + 1) < T;
        if (more) {
            a_ptr += BK;
            b_ptr += BK * FF;
            pa0 = *(const float4*)(a_ptr);
            pa1 = *(const float4*)(a_ptr + 4);
            pb0 = *(const float4*)(b_ptr);
            pb1 = *(const float4*)(b_ptr + 4);
        }

        #pragma unroll
        for (int k = 0; k < BK; k++) {
            float4 A0 = *(const float4*)&sA[buf][k * 128 + row0];
            float4 A1 = *(const float4*)&sA[buf][k * 128 + row0 + 4];
            float4 B0 = *(const float4*)&sB[buf][k * 128 + col0];
            float4 B1 = *(const float4*)&sB[buf][k * 128 + col0 + 4];
            float a[8] = {A0.x, A0.y, A0.z, A0.w, A1.x, A1.y, A1.z, A1.w};
            float b[8] = {B0.x, B0.y, B0.z, B0.w, B1.x, B1.y, B1.z, B1.w};
            #pragma unroll
            for (int i = 0; i < 8; i++)
                #pragma unroll
                for (int j = 0; j < 8; j++)
                    acc[i][j] = fmaf(a[i], b[j], acc[i][j]);
        }

        if (more) {
            int nbuf = buf ^ 1;
            float* s = &sA[nbuf][a_kq * 128 + a_row];
            s[0*128] = pa0.x; s[1*128] = pa0.y; s[2*128] = pa0.z; s[3*128] = pa0.w;
            s[4*128] = pa1.x; s[5*128] = pa1.y; s[6*128] = pa1.z; s[7*128] = pa1.w;
            *(float4*)&sB[nbuf][b_m * 128 + b_c]     = pb0;
            *(float4*)&sB[nbuf][b_m * 128 + b_c + 4] = pb1;
        }
        __syncthreads();
    }

    // epilogue: relu(dinv[n]*acc + bias[o]); out[b][n][o]
    int colg  = bx * 128 + col0;       // multiple of 8
    int bidx  = colg >> 6;
    int obase = colg & 63;             // <= 56, so 8 cols stay in one b-slice
    float bv[8];
    #pragma unroll
    for (int j = 0; j < 8; j++) bv[j] = bias[obase + j];

    #pragma unroll
    for (int i = 0; i < 8; i++) {
        int n = by * 128 + row0 + i;
        float dn = g_dinv[n];
        float* op = out + ((size_t)bidx << 18) + ((size_t)n << 6) + obase;
        float v[8];
        #pragma unroll
        for (int j = 0; j < 8; j++) {
            float t = fmaf(acc[i][j], dn, bv[j]);
            v[j] = fmaxf(t, 0.f);
        }
        *(float4*)(op)     = make_float4(v[0], v[1], v[2], v[3]);
        *(float4*)(op + 4) = make_float4(v[4], v[5], v[6], v[7]);
    }
}

// ---------------------------------------------------------------------------
// 4) adj passthrough into the output tail
// ---------------------------------------------------------------------------
__global__ void copy_adj(const float4* __restrict__ src, float4* __restrict__ dst, int n4) {
    int i = blockIdx.x * blockDim.x + threadIdx.x;
    if (i < n4) dst[i] = src[i];
}

// ---------------------------------------------------------------------------
extern "C" void kernel_launch(void* const* d_in, const int* in_sizes, int n_in,
                              void* d_out, int out_size) {
    const float* graph  = (const float*)d_in[0];   // [16,4096,64]
    const float* adj    = (const float*)d_in[1];   // [4096,4096]
    const float* weight = (const float*)d_in[2];   // [64,64]
    const float* bias   = (const float*)d_in[3];   // [64]
    float* out = (float*)d_out;

    rowsum_kernel<<<NN, 256>>>(adj);
    support_kernel<<<(BB * NN) / 64, 256>>>(graph, weight);
    gemm_kernel<<<dim3(8, 32), 256>>>(adj, bias, out);

    const int out_elems = BB * NN * FF;            // 4,194,304
    const int adj_elems = NN * NN;                 // 16,777,216
    if (out_size >= out_elems + adj_elems) {
        copy_adj<<<adj_elems / 4 / 256, 256>>>((const float4*)adj,
                                               (float4*)(out + out_elems),
                                               adj_elems / 4);
    }
}

// round 6
// speedup vs baseline: 1.3018x; 1.3018x over previous
#include <cuda_runtime.h>
#include <cuda_bf16.h>
#include <cstdint>

// GCN on GB300 (compiled for base sm_103: NO tcgen05, NO 'a'-suffix features).
// out = relu( D^-1/2 A D^-1/2 (G @ W) + bias ), plus verbatim adj copy.
// B=16, N=4096, F=64.
//
// Main GEMM C[4096 x 1024] = adj @ S2' via warp-level mma.sync (HMMA bf16,
// base PTX, sm_80+), bf16 hi/lo 3-pass split, fp32 accumulation:
//   x*y ~= xh*yh + xh*yl + xl*yh   (drops only ~2^-18 lo*lo terms)

#define NN 4096
#define FF 64
#define BB 16

// ---- scratch (static device arrays: allowed) ----
__device__ float g_dinv[NN];
__device__ __nv_bfloat16 g_adj_hi[(size_t)NN * NN];
__device__ __nv_bfloat16 g_adj_lo[(size_t)NN * NN];
__device__ __nv_bfloat16 g_bT_hi[(size_t)BB * FF * NN];   // [c=b*64+o][m]
__device__ __nv_bfloat16 g_bT_lo[(size_t)BB * FF * NN];

// ---------------------------------------------------------------------------
// helpers (base-PTX only)
// ---------------------------------------------------------------------------
__device__ __forceinline__ uint32_t smem_u32(const void* p) {
    uint32_t a;
    asm("{ .reg .u64 t; cvta.to.shared.u64 t, %1; cvt.u32.u64 %0, t; }" : "=r"(a) : "l"(p));
    return a;
}
#define CP_ASYNC16(dst, src) \
    asm volatile("cp.async.cg.shared.global [%0], [%1], 16;" :: "r"(dst), "l"(src) : "memory")
#define CP_COMMIT()  asm volatile("cp.async.commit_group;" ::: "memory")
#define CP_WAIT1()   asm volatile("cp.async.wait_group 1;" ::: "memory")
#define CP_WAIT0()   asm volatile("cp.async.wait_group 0;" ::: "memory")

__device__ __forceinline__ uint32_t lds32(uint32_t addr) {
    uint32_t v;
    asm volatile("ld.shared.b32 %0, [%1];" : "=r"(v) : "r"(addr));
    return v;
}

// D = A*B + D, m16n8k16, bf16 in / fp32 acc (base PTX, sm_80+)
#define MMA16816(c, a, b) \
    asm volatile("mma.sync.aligned.m16n8k16.row.col.f32.bf16.bf16.f32 " \
        "{%0,%1,%2,%3}, {%4,%5,%6,%7}, {%8,%9}, {%0,%1,%2,%3};" \
        : "+f"((c)[0]), "+f"((c)[1]), "+f"((c)[2]), "+f"((c)[3]) \
        : "r"((a)[0]), "r"((a)[1]), "r"((a)[2]), "r"((a)[3]), \
          "r"((b)[0]), "r"((b)[1]))

__device__ __forceinline__ uint32_t pack_bf2(__nv_bfloat16 a, __nv_bfloat16 b) {
    uint32_t lo = reinterpret_cast<unsigned short&>(a);
    uint32_t hi = reinterpret_cast<unsigned short&>(b);
    return lo | (hi << 16);
}

// ---------------------------------------------------------------------------
// 1) fused row sums -> d^{-1/2}  +  adj split into bf16 hi/lo
// ---------------------------------------------------------------------------
__global__ __launch_bounds__(256)
void rowsum_split_kernel(const float* __restrict__ adj) {
    __shared__ float red[8];
    int row = blockIdx.x;
    const float4* r = (const float4*)(adj + ((size_t)row << 12));
    uint2* oh = (uint2*)g_adj_hi + ((size_t)row << 10);
    uint2* ol = (uint2*)g_adj_lo + ((size_t)row << 10);
    float s = 0.f;
    for (int i = threadIdx.x; i < NN / 4; i += 256) {
        float4 v = r[i];
        s += (v.x + v.y) + (v.z + v.w);
        __nv_bfloat16 hx = __float2bfloat16_rn(v.x);
        __nv_bfloat16 hy = __float2bfloat16_rn(v.y);
        __nv_bfloat16 hz = __float2bfloat16_rn(v.z);
        __nv_bfloat16 hw = __float2bfloat16_rn(v.w);
        __nv_bfloat16 lx = __float2bfloat16_rn(v.x - __bfloat162float(hx));
        __nv_bfloat16 ly = __float2bfloat16_rn(v.y - __bfloat162float(hy));
        __nv_bfloat16 lz = __float2bfloat16_rn(v.z - __bfloat162float(hz));
        __nv_bfloat16 lw = __float2bfloat16_rn(v.w - __bfloat162float(hw));
        oh[i] = make_uint2(pack_bf2(hx, hy), pack_bf2(hz, hw));
        ol[i] = make_uint2(pack_bf2(lx, ly), pack_bf2(lz, lw));
    }
    #pragma unroll
    for (int off = 16; off; off >>= 1) s += __shfl_xor_sync(0xffffffffu, s, off);
    if ((threadIdx.x & 31) == 0) red[threadIdx.x >> 5] = s;
    __syncthreads();
    if (threadIdx.x < 8) {
        s = red[threadIdx.x];
        #pragma unroll
        for (int off = 4; off; off >>= 1) s += __shfl_xor_sync(0xffu, s, off);
        if (threadIdx.x == 0) {
            if (s == 0.f) s = 1.f;
            g_dinv[row] = rsqrtf(s);
        }
    }
}

// ---------------------------------------------------------------------------
// 2) support: S2'[c][m] = dinv[m] * (graph @ W)[b][m][o], TRANSPOSED bf16 hi/lo
// ---------------------------------------------------------------------------
__global__ __launch_bounds__(256)
void support_kernel(const float* __restrict__ graph, const float* __restrict__ weight) {
    __shared__ float gs[4][FF];
    __shared__ float Ssm[64][65];
    int tid = threadIdx.x;
    int o = tid & 63;
    int grp = tid >> 6;
    int b = blockIdx.y;
    int mb = blockIdx.x * 64;

    float w[FF];
    #pragma unroll
    for (int i = 0; i < FF; i++) w[i] = weight[i * FF + o];

    for (int it = 0; it < 16; it++) {
        int r = it * 4 + grp;
        gs[grp][o] = graph[(((size_t)b << 12) + mb + r) * FF + o];
        __syncthreads();
        float acc = 0.f;
        #pragma unroll
        for (int i = 0; i < FF; i++) acc = fmaf(gs[grp][i], w[i], acc);
        Ssm[r][o] = acc * g_dinv[mb + r];
        __syncthreads();
    }

    int o2 = tid >> 2;
    int rq = tid & 3;
    uint32_t ph[8], pl[8];
    #pragma unroll
    for (int p = 0; p < 8; p++) {
        float v0 = Ssm[rq * 16 + 2 * p][o2];
        float v1 = Ssm[rq * 16 + 2 * p + 1][o2];
        __nv_bfloat16 h0 = __float2bfloat16_rn(v0);
        __nv_bfloat16 h1 = __float2bfloat16_rn(v1);
        __nv_bfloat16 l0 = __float2bfloat16_rn(v0 - __bfloat162float(h0));
        __nv_bfloat16 l1 = __float2bfloat16_rn(v1 - __bfloat162float(h1));
        ph[p] = pack_bf2(h0, h1);
        pl[p] = pack_bf2(l0, l1);
    }
    size_t base = (((size_t)(b * 64 + o2)) << 12) + mb + rq * 16;
    uint4* dh = (uint4*)(g_bT_hi + base);
    uint4* dl = (uint4*)(g_bT_lo + base);
    dh[0] = make_uint4(ph[0], ph[1], ph[2], ph[3]);
    dh[1] = make_uint4(ph[4], ph[5], ph[6], ph[7]);
    dl[0] = make_uint4(pl[0], pl[1], pl[2], pl[3]);
    dl[1] = make_uint4(pl[4], pl[5], pl[6], pl[7]);
}

// ---------------------------------------------------------------------------
// 3) main GEMM via mma.sync: CTA 128x128, 8 warps (4m x 2n), warp tile 32x64.
//    smem stage = AH | AL | BH | BL, each 128 rows x 20 words (pad: rows of
//    32 bf16 padded to 40). Frag loads are conflict-free lds.b32
//    (bank = 20*row + tg mod 32 is a permutation over the 8x4 lane pattern).
// ---------------------------------------------------------------------------
#define BKK 32
#define KT_ITERS (NN / BKK)          // 128
#define VER_B 10240                  // 128 rows * 80B
#define STAGE_B (4 * VER_B)          // 40960
#define SMEM_DYN (2 * STAGE_B)       // 81920

__global__ __launch_bounds__(256, 1)
void gemm_mma_kernel(const float* __restrict__ bias, float* __restrict__ out) {
    extern __shared__ char smem[];
    __shared__ float s_bias[64];
    uint32_t sb = smem_u32(smem);
    int tid = threadIdx.x;
    int bx = blockIdx.x;      // 0..7  (128-col blocks)
    int by = blockIdx.y;      // 0..31 (128-row blocks)
    int wid = tid >> 5, lane = tid & 31;
    int wm = wid >> 1, wn = wid & 1;         // warp grid 4(m) x 2(n)
    int g = lane >> 2, tg = lane & 3;        // fragment group / quad ids

    if (tid < 64) s_bias[tid] = bias[tid];

    // ---- cp.async stage loader: 2048 x 16B chunks, 8 per thread ----
    auto load_stage = [&](int s, int kt) {
        uint32_t st = sb + (uint32_t)s * STAGE_B;
        int col0 = kt * BKK;
        #pragma unroll
        for (int q = tid; q < 2048; q += 256) {
            int region = q >> 9;           // 0=AH 1=AL 2=BH 3=BL
            int l = q & 511;
            int row = l >> 2;
            int c4 = l & 3;                // 16B chunk within 64B row
            const __nv_bfloat16* base =
                (region == 0) ? g_adj_hi :
                (region == 1) ? g_adj_lo :
                (region == 2) ? g_bT_hi  : g_bT_lo;
            int grow = ((region < 2) ? by : bx) * 128 + row;
            const __nv_bfloat16* src = base + ((size_t)grow << 12) + col0 + c4 * 8;
            uint32_t dst = st + (uint32_t)region * VER_B + row * 80 + c4 * 16;
            CP_ASYNC16(dst, src);
        }
        CP_COMMIT();
    };

    float acc[2][8][4];
    #pragma unroll
    for (int mi = 0; mi < 2; mi++)
        #pragma unroll
        for (int nj = 0; nj < 8; nj++)
            #pragma unroll
            for (int c = 0; c < 4; c++) acc[mi][nj][c] = 0.f;

    load_stage(0, 0);

    #pragma unroll 1
    for (int kt = 0; kt < KT_ITERS; kt++) {
        if (kt + 1 < KT_ITERS) {
            load_stage((kt + 1) & 1, kt + 1);
            CP_WAIT1();
        } else {
            CP_WAIT0();
        }
        __syncthreads();

        uint32_t st = sb + (uint32_t)(kt & 1) * STAGE_B;
        #pragma unroll
        for (int s = 0; s < 2; s++) {       // two k16 steps per BK=32
            uint32_t ah[2][4], al[2][4], bh[8][2], bl[8][2];
            #pragma unroll
            for (int mi = 0; mi < 2; mi++) {
                int r = wm * 32 + mi * 16 + g;
                uint32_t w0 = st + (uint32_t)(r * 20 + s * 8 + tg) * 4;
                ah[mi][0] = lds32(w0);
                ah[mi][1] = lds32(w0 + 160 * 4);   // +8 rows
                ah[mi][2] = lds32(w0 + 4 * 4);     // +8 k
                ah[mi][3] = lds32(w0 + 164 * 4);
                uint32_t w1 = w0 + VER_B;
                al[mi][0] = lds32(w1);
                al[mi][1] = lds32(w1 + 160 * 4);
                al[mi][2] = lds32(w1 + 4 * 4);
                al[mi][3] = lds32(w1 + 164 * 4);
            }
            #pragma unroll
            for (int nj = 0; nj < 8; nj++) {
                int n = wn * 64 + nj * 8 + g;
                uint32_t w0 = st + 2 * VER_B + (uint32_t)(n * 20 + s * 8 + tg) * 4;
                bh[nj][0] = lds32(w0);
                bh[nj][1] = lds32(w0 + 4 * 4);
                uint32_t w1 = w0 + VER_B;
                bl[nj][0] = lds32(w1);
                bl[nj][1] = lds32(w1 + 4 * 4);
            }
            #pragma unroll
            for (int mi = 0; mi < 2; mi++)
                #pragma unroll
                for (int nj = 0; nj < 8; nj++) MMA16816(acc[mi][nj], ah[mi], bh[nj]);
            #pragma unroll
            for (int mi = 0; mi < 2; mi++)
                #pragma unroll
                for (int nj = 0; nj < 8; nj++) MMA16816(acc[mi][nj], ah[mi], bl[nj]);
            #pragma unroll
            for (int mi = 0; mi < 2; mi++)
                #pragma unroll
                for (int nj = 0; nj < 8; nj++) MMA16816(acc[mi][nj], al[mi], bh[nj]);
        }
        __syncthreads();
    }

    // ---- epilogue: relu(dinv[n]*acc + bias[o]) -> out[b][n][o] ----
    int b_out = bx * 2 + wn;                      // batch slice (cols/64)
    float* obase = out + ((size_t)b_out << 18);
    #pragma unroll
    for (int mi = 0; mi < 2; mi++) {
        int r0 = by * 128 + wm * 32 + mi * 16 + g;
        int r1 = r0 + 8;
        float d0 = g_dinv[r0];
        float d1 = g_dinv[r1];
        #pragma unroll
        for (int nj = 0; nj < 8; nj++) {
            int o = nj * 8 + tg * 2;
            float bz0 = s_bias[o], bz1 = s_bias[o + 1];
            float2 v0, v1;
            v0.x = fmaxf(fmaf(acc[mi][nj][0], d0, bz0), 0.f);
            v0.y = fmaxf(fmaf(acc[mi][nj][1], d0, bz1), 0.f);
            v1.x = fmaxf(fmaf(acc[mi][nj][2], d1, bz0), 0.f);
            v1.y = fmaxf(fmaf(acc[mi][nj][3], d1, bz1), 0.f);
            *(float2*)(obase + ((size_t)r0 << 6) + o) = v0;
            *(float2*)(obase + ((size_t)r1 << 6) + o) = v1;
        }
    }
}

// ---------------------------------------------------------------------------
// 4) adj passthrough
// ---------------------------------------------------------------------------
__global__ void copy_adj(const float4* __restrict__ src, float4* __restrict__ dst, int n4) {
    int i = blockIdx.x * blockDim.x + threadIdx.x;
    if (i < n4) dst[i] = src[i];
}

// ---------------------------------------------------------------------------
extern "C" void kernel_launch(void* const* d_in, const int* in_sizes, int n_in,
                              void* d_out, int out_size) {
    const float* graph  = (const float*)d_in[0];   // [16,4096,64]
    const float* adj    = (const float*)d_in[1];   // [4096,4096]
    const float* weight = (const float*)d_in[2];   // [64,64]
    const float* bias   = (const float*)d_in[3];   // [64]
    float* out = (float*)d_out;

    cudaFuncSetAttribute(gemm_mma_kernel,
                         cudaFuncAttributeMaxDynamicSharedMemorySize, SMEM_DYN);

    rowsum_split_kernel<<<NN, 256>>>(adj);
    support_kernel<<<dim3(NN / 64, BB), 256>>>(graph, weight);
    gemm_mma_kernel<<<dim3(8, 32), 256, SMEM_DYN>>>(bias, out);

    const int out_elems = BB * NN * FF;
    const int adj_elems = NN * NN;
    if (out_size >= out_elems + adj_elems) {
        copy_adj<<<adj_elems / 4 / 256, 256>>>((const float4*)adj,
                                               (float4*)(out + out_elems),
                                               adj_elems / 4);
    }
}

// round 7
// speedup vs baseline: 3.7160x; 2.8544x over previous
#include <cuda_runtime.h>
#include <cuda_fp16.h>
#include <cstdint>

// GCN on GB300 (base sm_103 PTX only: mma.sync + cp.async, no tcgen05).
// out = relu( D^-1/2 A D^-1/2 (G @ W) + bias ), plus verbatim adj copy.
// B=16, N=4096, F=64.
//
// Main GEMM C[4096 x 1024] = adj @ S2' in SINGLE-PASS fp16 HMMA, fp32 acc.
// (R6 measured: bf16 3-pass split -> rel_err 2.0e-6; fp16 single-pass is
//  2^7x coarser -> predicted ~2.6e-4, safely under the 1e-3 gate.)

#define NN 4096
#define FF 64
#define BB 16

// ---- scratch (static device arrays: allowed) ----
__device__ float g_dinv[NN];
__device__ __half g_adj_h[(size_t)NN * NN];          // fp16 adj
__device__ __half g_bT_h[(size_t)BB * FF * NN];      // fp16 S2' [c=b*64+o][m], dinv folded

// ---------------------------------------------------------------------------
// helpers (base-PTX only)
// ---------------------------------------------------------------------------
__device__ __forceinline__ uint32_t smem_u32(const void* p) {
    uint32_t a;
    asm("{ .reg .u64 t; cvta.to.shared.u64 t, %1; cvt.u32.u64 %0, t; }" : "=r"(a) : "l"(p));
    return a;
}
#define CP_ASYNC16(dst, src) \
    asm volatile("cp.async.cg.shared.global [%0], [%1], 16;" :: "r"(dst), "l"(src) : "memory")
#define CP_COMMIT()  asm volatile("cp.async.commit_group;" ::: "memory")
#define CP_WAIT1()   asm volatile("cp.async.wait_group 1;" ::: "memory")
#define CP_WAIT0()   asm volatile("cp.async.wait_group 0;" ::: "memory")

__device__ __forceinline__ uint32_t lds32(uint32_t addr) {
    uint32_t v;
    asm volatile("ld.shared.b32 %0, [%1];" : "=r"(v) : "r"(addr));
    return v;
}

// D = A*B + D, m16n8k16, fp16 in / fp32 acc (base PTX, sm_80+)
#define MMA16816(c, a, b) \
    asm volatile("mma.sync.aligned.m16n8k16.row.col.f32.f16.f16.f32 " \
        "{%0,%1,%2,%3}, {%4,%5,%6,%7}, {%8,%9}, {%0,%1,%2,%3};" \
        : "+f"((c)[0]), "+f"((c)[1]), "+f"((c)[2]), "+f"((c)[3]) \
        : "r"((a)[0]), "r"((a)[1]), "r"((a)[2]), "r"((a)[3]), \
          "r"((b)[0]), "r"((b)[1]))

__device__ __forceinline__ uint32_t pack_h2(__half a, __half b) {
    uint32_t lo = reinterpret_cast<unsigned short&>(a);
    uint32_t hi = reinterpret_cast<unsigned short&>(b);
    return lo | (hi << 16);
}

// ---------------------------------------------------------------------------
// 1) fused row sums -> d^{-1/2}  +  adj -> fp16
// ---------------------------------------------------------------------------
__global__ __launch_bounds__(256)
void rowsum_split_kernel(const float* __restrict__ adj) {
    __shared__ float red[8];
    int row = blockIdx.x;
    const float4* r = (const float4*)(adj + ((size_t)row << 12));
    uint2* oh = (uint2*)g_adj_h + ((size_t)row << 10);   // 4 fp16 = 8B per float4
    float s = 0.f;
    for (int i = threadIdx.x; i < NN / 4; i += 256) {
        float4 v = r[i];
        s += (v.x + v.y) + (v.z + v.w);
        oh[i] = make_uint2(pack_h2(__float2half_rn(v.x), __float2half_rn(v.y)),
                           pack_h2(__float2half_rn(v.z), __float2half_rn(v.w)));
    }
    #pragma unroll
    for (int off = 16; off; off >>= 1) s += __shfl_xor_sync(0xffffffffu, s, off);
    if ((threadIdx.x & 31) == 0) red[threadIdx.x >> 5] = s;
    __syncthreads();
    if (threadIdx.x < 8) {
        s = red[threadIdx.x];
        #pragma unroll
        for (int off = 4; off; off >>= 1) s += __shfl_xor_sync(0xffu, s, off);
        if (threadIdx.x == 0) {
            if (s == 0.f) s = 1.f;
            g_dinv[row] = rsqrtf(s);
        }
    }
}

// ---------------------------------------------------------------------------
// 2) support: S2'[c][m] = dinv[m] * (graph @ W)[b][m][o], TRANSPOSED fp16
// ---------------------------------------------------------------------------
__global__ __launch_bounds__(256)
void support_kernel(const float* __restrict__ graph, const float* __restrict__ weight) {
    __shared__ float gs[4][FF];
    __shared__ float Ssm[64][65];
    int tid = threadIdx.x;
    int o = tid & 63;
    int grp = tid >> 6;
    int b = blockIdx.y;
    int mb = blockIdx.x * 64;

    float w[FF];
    #pragma unroll
    for (int i = 0; i < FF; i++) w[i] = weight[i * FF + o];

    for (int it = 0; it < 16; it++) {
        int r = it * 4 + grp;
        gs[grp][o] = graph[(((size_t)b << 12) + mb + r) * FF + o];
        __syncthreads();
        float acc = 0.f;
        #pragma unroll
        for (int i = 0; i < FF; i++) acc = fmaf(gs[grp][i], w[i], acc);
        Ssm[r][o] = acc * g_dinv[mb + r];
        __syncthreads();
    }

    int o2 = tid >> 2;
    int rq = tid & 3;
    uint32_t ph[8];
    #pragma unroll
    for (int p = 0; p < 8; p++) {
        float v0 = Ssm[rq * 16 + 2 * p][o2];
        float v1 = Ssm[rq * 16 + 2 * p + 1][o2];
        ph[p] = pack_h2(__float2half_rn(v0), __float2half_rn(v1));
    }
    size_t base = (((size_t)(b * 64 + o2)) << 12) + mb + rq * 16;
    uint4* dh = (uint4*)(g_bT_h + base);
    dh[0] = make_uint4(ph[0], ph[1], ph[2], ph[3]);
    dh[1] = make_uint4(ph[4], ph[5], ph[6], ph[7]);
}

// ---------------------------------------------------------------------------
// 3) main GEMM via fp16 mma.sync: CTA 128x128, 8 warps (4m x 2n), warp 32x64.
//    smem stage = A | B, each 128 rows x 20 words (32 fp16 padded to 40).
//    Frag lds.b32 banks: 20*g + tg (mod 32) all-distinct -> conflict-free.
//    2 CTAs/SM (41KB smem, ~110 regs) -> 4 warps/SMSP, 256 CTAs in 1 wave.
// ---------------------------------------------------------------------------
#define BKK 32
#define KT_ITERS (NN / BKK)          // 128
#define VER_B 10240                  // 128 rows * 80B
#define STAGE_B (2 * VER_B)          // 20480
#define SMEM_DYN (2 * STAGE_B)       // 40960

__global__ __launch_bounds__(256, 2)
void gemm_mma_kernel(const float* __restrict__ bias, float* __restrict__ out) {
    extern __shared__ char smem[];
    __shared__ float s_bias[64];
    uint32_t sb = smem_u32(smem);
    int tid = threadIdx.x;
    int bx = blockIdx.x;      // 0..7  (128-col blocks)
    int by = blockIdx.y;      // 0..31 (128-row blocks)
    int wid = tid >> 5, lane = tid & 31;
    int wm = wid >> 1, wn = wid & 1;         // warp grid 4(m) x 2(n)
    int g = lane >> 2, tg = lane & 3;        // fragment group / quad ids

    if (tid < 64) s_bias[tid] = bias[tid];

    // ---- cp.async stage loader: 1024 x 16B chunks, 4 per thread ----
    auto load_stage = [&](int s, int kt) {
        uint32_t st = sb + (uint32_t)s * STAGE_B;
        int col0 = kt * BKK;
        #pragma unroll
        for (int q = tid; q < 1024; q += 256) {
            int region = q >> 9;           // 0=A 1=B
            int l = q & 511;
            int row = l >> 2;
            int c4 = l & 3;                // 16B chunk within 64B row
            const __half* base = region ? g_bT_h : g_adj_h;
            int grow = (region ? bx : by) * 128 + row;
            const __half* src = base + ((size_t)grow << 12) + col0 + c4 * 8;
            uint32_t dst = st + (uint32_t)region * VER_B + row * 80 + c4 * 16;
            CP_ASYNC16(dst, src);
        }
        CP_COMMIT();
    };

    float acc[2][8][4];
    #pragma unroll
    for (int mi = 0; mi < 2; mi++)
        #pragma unroll
        for (int nj = 0; nj < 8; nj++)
            #pragma unroll
            for (int c = 0; c < 4; c++) acc[mi][nj][c] = 0.f;

    load_stage(0, 0);

    #pragma unroll 1
    for (int kt = 0; kt < KT_ITERS; kt++) {
        if (kt + 1 < KT_ITERS) {
            load_stage((kt + 1) & 1, kt + 1);
            CP_WAIT1();
        } else {
            CP_WAIT0();
        }
        __syncthreads();

        uint32_t st = sb + (uint32_t)(kt & 1) * STAGE_B;
        #pragma unroll
        for (int s = 0; s < 2; s++) {       // two k16 steps per BK=32
            uint32_t ah[2][4], bh[8][2];
            #pragma unroll
            for (int mi = 0; mi < 2; mi++) {
                int r = wm * 32 + mi * 16 + g;
                uint32_t w0 = st + (uint32_t)(r * 20 + s * 8 + tg) * 4;
                ah[mi][0] = lds32(w0);
                ah[mi][1] = lds32(w0 + 160 * 4);   // +8 rows
                ah[mi][2] = lds32(w0 + 4 * 4);     // +8 k
                ah[mi][3] = lds32(w0 + 164 * 4);
            }
            #pragma unroll
            for (int nj = 0; nj < 8; nj++) {
                int n = wn * 64 + nj * 8 + g;
                uint32_t w0 = st + VER_B + (uint32_t)(n * 20 + s * 8 + tg) * 4;
                bh[nj][0] = lds32(w0);
                bh[nj][1] = lds32(w0 + 4 * 4);
            }
            #pragma unroll
            for (int mi = 0; mi < 2; mi++)
                #pragma unroll
                for (int nj = 0; nj < 8; nj++) MMA16816(acc[mi][nj], ah[mi], bh[nj]);
        }
        __syncthreads();
    }

    // ---- epilogue: relu(dinv[n]*acc + bias[o]) -> out[b][n][o] ----
    int b_out = bx * 2 + wn;                      // batch slice (cols/64)
    float* obase = out + ((size_t)b_out << 18);
    #pragma unroll
    for (int mi = 0; mi < 2; mi++) {
        int r0 = by * 128 + wm * 32 + mi * 16 + g;
        int r1 = r0 + 8;
        float d0 = g_dinv[r0];
        float d1 = g_dinv[r1];
        #pragma unroll
        for (int nj = 0; nj < 8; nj++) {
            int o = nj * 8 + tg * 2;
            float bz0 = s_bias[o], bz1 = s_bias[o + 1];
            float2 v0, v1;
            v0.x = fmaxf(fmaf(acc[mi][nj][0], d0, bz0), 0.f);
            v0.y = fmaxf(fmaf(acc[mi][nj][1], d0, bz1), 0.f);
            v1.x = fmaxf(fmaf(acc[mi][nj][2], d1, bz0), 0.f);
            v1.y = fmaxf(fmaf(acc[mi][nj][3], d1, bz1), 0.f);
            *(float2*)(obase + ((size_t)r0 << 6) + o) = v0;
            *(float2*)(obase + ((size_t)r1 << 6) + o) = v1;
        }
    }
}

// ---------------------------------------------------------------------------
// 4) adj passthrough
// ---------------------------------------------------------------------------
__global__ void copy_adj(const float4* __restrict__ src, float4* __restrict__ dst, int n4) {
    int i = blockIdx.x * blockDim.x + threadIdx.x;
    if (i < n4) dst[i] = src[i];
}

// ---------------------------------------------------------------------------
extern "C" void kernel_launch(void* const* d_in, const int* in_sizes, int n_in,
                              void* d_out, int out_size) {
    const float* graph  = (const float*)d_in[0];   // [16,4096,64]
    const float* adj    = (const float*)d_in[1];   // [4096,4096]
    const float* weight = (const float*)d_in[2];   // [64,64]
    const float* bias   = (const float*)d_in[3];   // [64]
    float* out = (float*)d_out;

    cudaFuncSetAttribute(gemm_mma_kernel,
                         cudaFuncAttributeMaxDynamicSharedMemorySize, SMEM_DYN);

    rowsum_split_kernel<<<NN, 256>>>(adj);
    support_kernel<<<dim3(NN / 64, BB), 256>>>(graph, weight);
    gemm_mma_kernel<<<dim3(8, 32), 256, SMEM_DYN>>>(bias, out);

    const int out_elems = BB * NN * FF;
    const int adj_elems = NN * NN;
    if (out_size >= out_elems + adj_elems) {
        copy_adj<<<adj_elems / 4 / 256, 256>>>((const float4*)adj,
                                               (float4*)(out + out_elems),
                                               adj_elems / 4);
    }
}

// round 8
// speedup vs baseline: 4.7032x; 1.2657x over previous
#include <cuda_runtime.h>
#include <cuda_fp16.h>
#include <cstdint>

// GCN on GB300 (base sm_103 PTX only: mma.sync + ldmatrix + cp.async).
// out = relu( D^-1/2 A D^-1/2 (G @ W) + bias ), plus verbatim adj copy.
// B=16, N=4096, F=64.
// Main GEMM C[4096 x 1024] = adj @ S2' in single-pass fp16 HMMA, fp32 acc.

#define NN 4096
#define FF 64
#define BB 16

// ---- scratch (static device arrays: allowed) ----
__device__ float g_dinv[NN];
__device__ __half g_adj_h[(size_t)NN * NN];          // fp16 adj
__device__ __half g_bT_h[(size_t)BB * FF * NN];      // fp16 S2' [c=b*64+o][m], dinv folded

// ---------------------------------------------------------------------------
// helpers (base-PTX only)
// ---------------------------------------------------------------------------
__device__ __forceinline__ uint32_t smem_u32(const void* p) {
    uint32_t a;
    asm("{ .reg .u64 t; cvta.to.shared.u64 t, %1; cvt.u32.u64 %0, t; }" : "=r"(a) : "l"(p));
    return a;
}
#define CP_ASYNC16(dst, src) \
    asm volatile("cp.async.cg.shared.global [%0], [%1], 16;" :: "r"(dst), "l"(src) : "memory")
#define CP_COMMIT()  asm volatile("cp.async.commit_group;" ::: "memory")
#define CP_WAIT1()   asm volatile("cp.async.wait_group 1;" ::: "memory")
#define CP_WAIT0()   asm volatile("cp.async.wait_group 0;" ::: "memory")

#define LDMATRIX_X4(r0, r1, r2, r3, addr) \
    asm volatile("ldmatrix.sync.aligned.m8n8.x4.shared.b16 {%0,%1,%2,%3}, [%4];" \
        : "=r"(r0), "=r"(r1), "=r"(r2), "=r"(r3) : "r"(addr))

// D = A*B + D, m16n8k16, fp16 in / fp32 acc (base PTX, sm_80+)
#define MMA16816(c, a, b) \
    asm volatile("mma.sync.aligned.m16n8k16.row.col.f32.f16.f16.f32 " \
        "{%0,%1,%2,%3}, {%4,%5,%6,%7}, {%8,%9}, {%0,%1,%2,%3};" \
        : "+f"((c)[0]), "+f"((c)[1]), "+f"((c)[2]), "+f"((c)[3]) \
        : "r"((a)[0]), "r"((a)[1]), "r"((a)[2]), "r"((a)[3]), \
          "r"((b)[0]), "r"((b)[1]))

__device__ __forceinline__ uint32_t pack_h2(__half a, __half b) {
    uint32_t lo = reinterpret_cast<unsigned short&>(a);
    uint32_t hi = reinterpret_cast<unsigned short&>(b);
    return lo | (hi << 16);
}

// ---------------------------------------------------------------------------
// 1) fused: row sums -> d^{-1/2}  +  adj -> fp16  +  adj -> output tail copy
// ---------------------------------------------------------------------------
__global__ __launch_bounds__(256)
void rowsum_split_copy_kernel(const float* __restrict__ adj, float* __restrict__ out_tail) {
    __shared__ float red[8];
    int row = blockIdx.x;
    const float4* r = (const float4*)(adj + ((size_t)row << 12));
    float4* cp = (float4*)(out_tail + ((size_t)row << 12));
    uint2* oh = (uint2*)g_adj_h + ((size_t)row << 10);
    float s = 0.f;
    for (int i = threadIdx.x; i < NN / 4; i += 256) {
        float4 v = r[i];
        s += (v.x + v.y) + (v.z + v.w);
        oh[i] = make_uint2(pack_h2(__float2half_rn(v.x), __float2half_rn(v.y)),
                           pack_h2(__float2half_rn(v.z), __float2half_rn(v.w)));
        cp[i] = v;
    }
    #pragma unroll
    for (int off = 16; off; off >>= 1) s += __shfl_xor_sync(0xffffffffu, s, off);
    if ((threadIdx.x & 31) == 0) red[threadIdx.x >> 5] = s;
    __syncthreads();
    if (threadIdx.x < 8) {
        s = red[threadIdx.x];
        #pragma unroll
        for (int off = 4; off; off >>= 1) s += __shfl_xor_sync(0xffu, s, off);
        if (threadIdx.x == 0) {
            if (s == 0.f) s = 1.f;
            g_dinv[row] = rsqrtf(s);
        }
    }
}

// ---------------------------------------------------------------------------
// 2) support: S2'[c][m] = dinv[m] * (graph @ W)[b][m][o], TRANSPOSED fp16
// ---------------------------------------------------------------------------
__global__ __launch_bounds__(256)
void support_kernel(const float* __restrict__ graph, const float* __restrict__ weight) {
    __shared__ float gs[4][FF];
    __shared__ float Ssm[64][65];
    int tid = threadIdx.x;
    int o = tid & 63;
    int grp = tid >> 6;
    int b = blockIdx.y;
    int mb = blockIdx.x * 64;

    float w[FF];
    #pragma unroll
    for (int i = 0; i < FF; i++) w[i] = weight[i * FF + o];

    for (int it = 0; it < 16; it++) {
        int r = it * 4 + grp;
        gs[grp][o] = graph[(((size_t)b << 12) + mb + r) * FF + o];
        __syncthreads();
        float acc = 0.f;
        #pragma unroll
        for (int i = 0; i < FF; i++) acc = fmaf(gs[grp][i], w[i], acc);
        Ssm[r][o] = acc * g_dinv[mb + r];
        __syncthreads();
    }

    int o2 = tid >> 2;
    int rq = tid & 3;
    uint32_t ph[8];
    #pragma unroll
    for (int p = 0; p < 8; p++) {
        float v0 = Ssm[rq * 16 + 2 * p][o2];
        float v1 = Ssm[rq * 16 + 2 * p + 1][o2];
        ph[p] = pack_h2(__float2half_rn(v0), __float2half_rn(v1));
    }
    size_t base = (((size_t)(b * 64 + o2)) << 12) + mb + rq * 16;
    uint4* dh = (uint4*)(g_bT_h + base);
    dh[0] = make_uint4(ph[0], ph[1], ph[2], ph[3]);
    dh[1] = make_uint4(ph[4], ph[5], ph[6], ph[7]);
}

// ---------------------------------------------------------------------------
// 3) main GEMM: CTA 128x128, 8 warps (4m x 2n), warp 32x64, BK=64, 2 stages.
//    smem rows padded to 144B (64 fp16 + 8 pad): ldmatrix phases hit banks
//    4r mod 32 -> conflict-free. Fragment loads via ldmatrix.x4.
// ---------------------------------------------------------------------------
#define BKK 64
#define KT_ITERS (NN / BKK)          // 64
#define ROW_B 144
#define VER_B (128 * ROW_B)          // 18432
#define STAGE_B (2 * VER_B)          // 36864
#define SMEM_DYN (2 * STAGE_B)       // 73728

__global__ __launch_bounds__(256, 2)
void gemm_mma_kernel(const float* __restrict__ bias, float* __restrict__ out) {
    extern __shared__ char smem[];
    __shared__ float s_bias[64];
    uint32_t sb = smem_u32(smem);
    int tid = threadIdx.x;
    int bx = blockIdx.x;      // 0..7  (128-col blocks)
    int by = blockIdx.y;      // 0..31 (128-row blocks)
    int wid = tid >> 5, lane = tid & 31;
    int wm = wid >> 1, wn = wid & 1;         // warp grid 4(m) x 2(n)
    int g = lane >> 2, tg = lane & 3;        // epilogue frag ids

    if (tid < 64) s_bias[tid] = bias[tid];

    // ---- cp.async stage loader: 2048 x 16B chunks, 8 per thread ----
    auto load_stage = [&](int s, int kt) {
        uint32_t st = sb + (uint32_t)s * STAGE_B;
        int col0 = kt * BKK;                 // half-elem offset along K
        #pragma unroll
        for (int q = tid; q < 2048; q += 256) {
            int region = q >> 10;            // 0=A 1=B
            int l = q & 1023;
            int row = l >> 3;
            int c = l & 7;                   // 16B chunk within 128B of data
            const __half* base = region ? g_bT_h : g_adj_h;
            int grow = (region ? bx : by) * 128 + row;
            const __half* src = base + ((size_t)grow << 12) + col0 + c * 8;
            uint32_t dst = st + (uint32_t)region * VER_B + row * ROW_B + c * 16;
            CP_ASYNC16(dst, src);
        }
        CP_COMMIT();
    };

    // ldmatrix lane-address components (warp-invariant per lane)
    // A: rows m = wm*32 + mi*16 + (lane&7) + ((lane>>3)&1)*8 ; half-col = s*16 + (lane>>4)*8
    int a_row_l = (lane & 7) + ((lane >> 3) & 1) * 8;
    int a_colh_l = (lane >> 4) * 8;
    // B: rows n = wn*64 + p*16 + ((lane>>4)&1)*8 + (lane&7) ; half-col = s*16 + ((lane>>3)&1)*8
    int b_row_l = ((lane >> 4) & 1) * 8 + (lane & 7);
    int b_colh_l = ((lane >> 3) & 1) * 8;

    float acc[2][8][4];
    #pragma unroll
    for (int mi = 0; mi < 2; mi++)
        #pragma unroll
        for (int nj = 0; nj < 8; nj++)
            #pragma unroll
            for (int c = 0; c < 4; c++) acc[mi][nj][c] = 0.f;

    load_stage(0, 0);

    #pragma unroll 1
    for (int kt = 0; kt < KT_ITERS; kt++) {
        if (kt + 1 < KT_ITERS) {
            load_stage((kt + 1) & 1, kt + 1);
            CP_WAIT1();
        } else {
            CP_WAIT0();
        }
        __syncthreads();

        uint32_t st = sb + (uint32_t)(kt & 1) * STAGE_B;
        uint32_t aBase = st + (uint32_t)((wm * 32 + a_row_l) * ROW_B + a_colh_l * 2);
        uint32_t bBase = st + VER_B + (uint32_t)((wn * 64 + b_row_l) * ROW_B + b_colh_l * 2);

        #pragma unroll
        for (int s = 0; s < 4; s++) {        // four k16 steps per BK=64
            uint32_t ah[2][4], bh[8][2];
            #pragma unroll
            for (int mi = 0; mi < 2; mi++) {
                uint32_t addr = aBase + (uint32_t)(mi * 16 * ROW_B + s * 32);
                LDMATRIX_X4(ah[mi][0], ah[mi][1], ah[mi][2], ah[mi][3], addr);
            }
            #pragma unroll
            for (int p = 0; p < 4; p++) {    // each x4 covers nj=2p, 2p+1
                uint32_t addr = bBase + (uint32_t)(p * 16 * ROW_B + s * 32);
                LDMATRIX_X4(bh[2 * p][0], bh[2 * p][1], bh[2 * p + 1][0], bh[2 * p + 1][1], addr);
            }
            #pragma unroll
            for (int mi = 0; mi < 2; mi++)
                #pragma unroll
                for (int nj = 0; nj < 8; nj++) MMA16816(acc[mi][nj], ah[mi], bh[nj]);
        }
        __syncthreads();
    }

    // ---- epilogue: relu(dinv[n]*acc + bias[o]) -> out[b][n][o] ----
    int b_out = bx * 2 + wn;                      // batch slice (cols/64)
    float* obase = out + ((size_t)b_out << 18);
    #pragma unroll
    for (int mi = 0; mi < 2; mi++) {
        int r0 = by * 128 + wm * 32 + mi * 16 + g;
        int r1 = r0 + 8;
        float d0 = g_dinv[r0];
        float d1 = g_dinv[r1];
        #pragma unroll
        for (int nj = 0; nj < 8; nj++) {
            int o = nj * 8 + tg * 2;
            float bz0 = s_bias[o], bz1 = s_bias[o + 1];
            float2 v0, v1;
            v0.x = fmaxf(fmaf(acc[mi][nj][0], d0, bz0), 0.f);
            v0.y = fmaxf(fmaf(acc[mi][nj][1], d0, bz1), 0.f);
            v1.x = fmaxf(fmaf(acc[mi][nj][2], d1, bz0), 0.f);
            v1.y = fmaxf(fmaf(acc[mi][nj][3], d1, bz1), 0.f);
            *(float2*)(obase + ((size_t)r0 << 6) + o) = v0;
            *(float2*)(obase + ((size_t)r1 << 6) + o) = v1;
        }
    }
}

// ---------------------------------------------------------------------------
extern "C" void kernel_launch(void* const* d_in, const int* in_sizes, int n_in,
                              void* d_out, int out_size) {
    const float* graph  = (const float*)d_in[0];   // [16,4096,64]
    const float* adj    = (const float*)d_in[1];   // [4096,4096]
    const float* weight = (const float*)d_in[2];   // [64,64]
    const float* bias   = (const float*)d_in[3];   // [64]
    float* out = (float*)d_out;

    cudaFuncSetAttribute(gemm_mma_kernel,
                         cudaFuncAttributeMaxDynamicSharedMemorySize, SMEM_DYN);

    const int out_elems = BB * NN * FF;            // 4,194,304
    float* tail = out + out_elems;                 // adj copy destination

    rowsum_split_copy_kernel<<<NN, 256>>>(adj, tail);
    support_kernel<<<dim3(NN / 64, BB), 256>>>(graph, weight);
    gemm_mma_kernel<<<dim3(8, 32), 256, SMEM_DYN>>>(bias, out);
}